// round 1
// baseline (speedup 1.0000x reference)
#include <cuda_runtime.h>
#include <math.h>

#define BB 16
#define TT 800
#define LL 160
#define DD 80
#define KK2 (2*DD)          // GEMM K dimension = 160
#define NEG_INFF (-1e20f)
#define HALF_LOG2PI 0.9189385332046727f   // 0.5*log(2*pi)

// Scratch (no cudaMalloc allowed): W [b][k][l], k in [0,160): first 80 = -0.5*inv_var,
// next 80 = mu*inv_var.  C[b][l] = -0.5*q_mu - 0.5*sum(log_sigma) - 0.5*D*log(2pi)
__device__ float g_W[BB * KK2 * LL];
__device__ float g_C[BB * LL];

// ---------------------------------------------------------------------------
// K0: per-(b,l) parameter transform. One warp per (b,l); 2560 warps total.
// ---------------------------------------------------------------------------
__global__ void param_kernel(const float* __restrict__ mu_sigma) {
    int wl   = (blockIdx.x * blockDim.x + threadIdx.x) >> 5;
    int lane = threadIdx.x & 31;
    if (wl >= BB * LL) return;
    int b = wl / LL, l = wl % LL;
    const float* ms = mu_sigma + (size_t)(b * LL + l) * KK2;

    float qmu = 0.f, sl = 0.f;
    for (int d = lane; d < DD; d += 32) {
        float mu = 4.f / (1.f + __expf(-ms[d]));        // sigmoid(x)*4
        float ls = 4.f * tanhf(ms[DD + d]);             // tanh(x)*4
        float iv = __expf(-2.f * ls);                   // exp(-2*log_sigma)
        g_W[((size_t)b * KK2 + d)      * LL + l] = -0.5f * iv;
        g_W[((size_t)b * KK2 + DD + d) * LL + l] = mu * iv;
        qmu += mu * mu * iv;
        sl  += ls;
    }
#pragma unroll
    for (int o = 16; o; o >>= 1) {
        qmu += __shfl_xor_sync(0xffffffffu, qmu, o);
        sl  += __shfl_xor_sync(0xffffffffu, sl, o);
    }
    if (lane == 0)
        g_C[b * LL + l] = -0.5f * qmu - 0.5f * sl - (float)DD * HALF_LOG2PI;
}

// ---------------------------------------------------------------------------
// K1: log_prob as batched SGEMM: lp[b,t,l] = sum_k X[t,k]*W[k,l] + C[l]
// X[t,k] = mel[t,k]^2 (k<80) or mel[t,k-80] (k>=80), built on the fly.
// 64x64 tile, 256 threads, 4x4 per thread, BK=16 (K=160 -> 10 iters exact).
// ---------------------------------------------------------------------------
#define BK 16
__global__ void __launch_bounds__(256) lp_gemm(const float* __restrict__ mel,
                                               float* __restrict__ lp_out) {
    __shared__ float As[64][BK + 1];
    __shared__ float Bs[BK][64];

    int b  = blockIdx.z;
    int m0 = blockIdx.x * 64;
    int n0 = blockIdx.y * 64;
    int tid = threadIdx.x;
    int tx = tid & 15, ty = tid >> 4;

    const float* melb = mel + (size_t)b * TT * DD;
    const float* Wb   = g_W + (size_t)b * KK2 * LL;

    float acc[4][4];
#pragma unroll
    for (int i = 0; i < 4; i++)
#pragma unroll
        for (int j = 0; j < 4; j++) acc[i][j] = 0.f;

    for (int k0 = 0; k0 < KK2; k0 += BK) {
        bool sq = (k0 < DD);
        int  kc = sq ? k0 : (k0 - DD);   // mel column base; tile never straddles 80
        // Load A tile (64 rows of t x 16 k): coalesced 16-float runs per row.
#pragma unroll
        for (int i = 0; i < 4; i++) {
            int lin = tid + i * 256;
            int mm = lin >> 4, kk = lin & 15;
            int t = m0 + mm; if (t > TT - 1) t = TT - 1;   // clamp (guard at store)
            float v = melb[(size_t)t * DD + kc + kk];
            As[mm][kk] = sq ? v * v : v;
        }
        // Load B tile (16 k x 64 l): coalesced over l.
#pragma unroll
        for (int i = 0; i < 4; i++) {
            int lin = tid + i * 256;
            int kk = lin >> 6, nn = lin & 63;
            int l = n0 + nn;
            Bs[kk][nn] = (l < LL) ? Wb[(size_t)(k0 + kk) * LL + l] : 0.f;
        }
        __syncthreads();
#pragma unroll
        for (int kk = 0; kk < BK; kk++) {
            float a0 = As[ty * 4 + 0][kk];
            float a1 = As[ty * 4 + 1][kk];
            float a2 = As[ty * 4 + 2][kk];
            float a3 = As[ty * 4 + 3][kk];
            float4 bv = *(const float4*)&Bs[kk][tx * 4];
            acc[0][0] += a0 * bv.x; acc[0][1] += a0 * bv.y; acc[0][2] += a0 * bv.z; acc[0][3] += a0 * bv.w;
            acc[1][0] += a1 * bv.x; acc[1][1] += a1 * bv.y; acc[1][2] += a1 * bv.z; acc[1][3] += a1 * bv.w;
            acc[2][0] += a2 * bv.x; acc[2][1] += a2 * bv.y; acc[2][2] += a2 * bv.z; acc[2][3] += a2 * bv.w;
            acc[3][0] += a3 * bv.x; acc[3][1] += a3 * bv.y; acc[3][2] += a3 * bv.z; acc[3][3] += a3 * bv.w;
        }
        __syncthreads();
    }

#pragma unroll
    for (int i = 0; i < 4; i++) {
        int t = m0 + ty * 4 + i;
        if (t >= TT) continue;
#pragma unroll
        for (int j = 0; j < 4; j++) {
            int l = n0 + tx * 4 + j;
            if (l < LL)
                lp_out[((size_t)b * TT + t) * LL + l] = acc[i][j] + g_C[b * LL + l];
        }
    }
}

// ---------------------------------------------------------------------------
// K2: sequential alpha scan. One block per batch, 160 threads (one per l).
// Neighbor alpha[l-1] via shfl.up within warps; cross-warp boundary via a
// double-buffered 5-entry shared array + one __syncthreads per time step.
// ---------------------------------------------------------------------------
__device__ __forceinline__ float logaddexpf_(float a, float b) {
    float m = fmaxf(a, b);
    float d = fminf(a, b) - m;          // <= 0
    return m + __logf(1.f + __expf(d));
}

__global__ void __launch_bounds__(LL) scan_kernel(const float* __restrict__ lp,
                                                  float* __restrict__ alphas) {
    int b = blockIdx.x;
    int l = threadIdx.x;
    int warp = l >> 5, lane = l & 31;
    __shared__ float sb[2][5];

    const float* lpb = lp + (size_t)b * TT * LL;
    float* ab = alphas + (size_t)b * TT * LL;

    float alpha = (l == 0) ? lpb[0] : NEG_INFF;
    ab[l] = alpha;
    if (lane == 31) sb[0][warp] = alpha;

    // depth-2 prefetch of lp rows
    float lpn0 = lpb[(size_t)1 * LL + l];
    float lpn1 = lpb[(size_t)2 * LL + l];
    __syncthreads();

    for (int t = 1; t < TT; t++) {
        float lpv = lpn0;
        lpn0 = lpn1;
        lpn1 = (t + 2 < TT) ? lpb[(size_t)(t + 2) * LL + l] : 0.f;

        float up   = __shfl_up_sync(0xffffffffu, alpha, 1);
        float prev = lane ? up : (warp ? sb[(t - 1) & 1][warp - 1] : NEG_INFF);
        alpha = logaddexpf_(alpha, prev) + lpv;

        if (lane == 31) sb[t & 1][warp] = alpha;
        ab[(size_t)t * LL + l] = alpha;
        __syncthreads();
    }
}

// ---------------------------------------------------------------------------
// K3: loss = -mean(alphas[b, ml[b]-1, cl[b]-1])
// ---------------------------------------------------------------------------
__global__ void loss_kernel(const float* __restrict__ alphas,
                            const int* __restrict__ ml,
                            const int* __restrict__ cl,
                            float* __restrict__ out_loss) {
    int lane = threadIdx.x;
    float v = 0.f;
    if (lane < BB) {
        int t = ml[lane] - 1, l = cl[lane] - 1;
        v = alphas[((size_t)lane * TT + t) * LL + l];
    }
#pragma unroll
    for (int o = 16; o; o >>= 1) v += __shfl_xor_sync(0xffffffffu, v, o);
    if (lane == 0) out_loss[0] = -v / (float)BB;
}

// ---------------------------------------------------------------------------
extern "C" void kernel_launch(void* const* d_in, const int* in_sizes, int n_in,
                              void* d_out, int out_size) {
    const float* mel      = (const float*)d_in[0];
    const float* mu_sigma = (const float*)d_in[1];
    const int*   ml       = (const int*)d_in[2];
    const int*   cl       = (const int*)d_in[3];

    float* out    = (float*)d_out;
    float* lp     = out;                              // [B,T,L]
    float* loss   = out + (size_t)BB * TT * LL;       // [1]
    float* alphas = loss + 1;                         // [B,T,L]

    param_kernel<<<(BB * LL * 32 + 127) / 128, 128>>>(mu_sigma);

    dim3 g((TT + 63) / 64, (LL + 63) / 64, BB);       // 13 x 3 x 16
    lp_gemm<<<g, 256>>>(mel, lp);

    scan_kernel<<<BB, LL>>>(lp, alphas);

    loss_kernel<<<1, 32>>>(alphas, ml, cl, loss);
}